// round 15
// baseline (speedup 1.0000x reference)
#include <cuda_runtime.h>
#include <cuda_fp16.h>
#include <math.h>
#include <stdint.h>

// Problem constants
#define BB 131072
#define DD 64
#define KK 1024
#define DECAYF 0.99f
#define OMDF 0.01f
#define EPSV 1e-5f
// |z.e_lo| <= ~2^-11 -> certify top-4 when approx top1 - top4 > 2*bound
#define MARGINF 6.0e-4f

// ---------------- scratch ----------------
__device__ float    g_en[KK * DD];        // normalized embedding fp32 (exact rescore)
__device__ unsigned g_ehf[KK * 32];       // e_hi rows as fp16x2 (64 fp16 -> 32 u32 per code)
__device__ float    g_counts[KK];
__device__ float    g_dw[KK * DD];
__device__ float    g_embed_unit[KK * DD];
__device__ float    g_znorm[BB];
__device__ int      g_codes[BB];
__device__ int4     g_cand[BB];           // top-4 approx candidates per row
__device__ int      g_flag[BB];           // 1 = margin not certified -> full exact scan

// ---------------- helpers ----------------
__device__ __forceinline__ float warpsum(float v) {
#pragma unroll
    for (int o = 16; o; o >>= 1) v += __shfl_xor_sync(0xffffffffu, v, o);
    return v;
}
__device__ __forceinline__ float group16sum(float v) {
#pragma unroll
    for (int o = 8; o; o >>= 1) v += __shfl_xor_sync(0xffffffffu, v, o);
    return v;
}
__device__ __forceinline__ uint32_t smem_u32(const void* p) {
    uint32_t a;
    asm("{ .reg .u64 t; cvta.to.shared.u64 t, %1; cvt.u32.u64 %0, t; }" : "=r"(a) : "l"(p));
    return a;
}
__device__ __forceinline__ unsigned pack2h(__half a, __half b) {
    __half2 h = __halves2half2(a, b);
    return *reinterpret_cast<unsigned*>(&h);
}
// sorted top-4 insert, tie -> lower index (first-occurrence argmax semantics)
__device__ __forceinline__ void ins4(float v, int i, float* V, int* I) {
    bool b0 = (v > V[0]) || (v == V[0] && i < I[0]);
    bool b1 = (v > V[1]) || (v == V[1] && i < I[1]);
    bool b2 = (v > V[2]) || (v == V[2] && i < I[2]);
    bool b3 = (v > V[3]) || (v == V[3] && i < I[3]);
    if (b0)      { V[3]=V[2];I[3]=I[2]; V[2]=V[1];I[2]=I[1]; V[1]=V[0];I[1]=I[0]; V[0]=v;I[0]=i; }
    else if (b1) { V[3]=V[2];I[3]=I[2]; V[2]=V[1];I[2]=I[1]; V[1]=v;I[1]=i; }
    else if (b2) { V[3]=V[2];I[3]=I[2]; V[2]=v;I[2]=i; }
    else if (b3) { V[3]=v;I[3]=i; }
}
#define LDSM4(r0, r1, r2, r3, addr) \
    asm volatile("ldmatrix.sync.aligned.m8n8.x4.shared.b16 {%0,%1,%2,%3}, [%4];" \
        : "=r"(r0), "=r"(r1), "=r"(r2), "=r"(r3) : "r"(addr))
#define MMA16816(c, a, b0, b1) \
    asm volatile("mma.sync.aligned.m16n8k16.row.col.f32.f16.f16.f32 " \
        "{%0,%1,%2,%3}, {%4,%5,%6,%7}, {%8,%9}, {%0,%1,%2,%3};" \
        : "+f"((c)[0]), "+f"((c)[1]), "+f"((c)[2]), "+f"((c)[3]) \
        : "r"((a)[0]), "r"((a)[1]), "r"((a)[2]), "r"((a)[3]), "r"(b0), "r"(b1))

// ---------------- kernel 1: prep = zero scratch + normalize embedding ----------------
#define ZERO_BLOCKS 260
__global__ void k_prep(const float* __restrict__ emb) {
    int bid = blockIdx.x;
    if (bid < ZERO_BLOCKS) {
        int idx = bid * 256 + threadIdx.x;
        if (idx < KK * DD) g_dw[idx] = 0.0f;
        else if (idx < KK * DD + KK) g_counts[idx - KK * DD] = 0.0f;
        return;
    }
    int w = (bid - ZERO_BLOCKS) * 8 + (threadIdx.x >> 5);
    int lane = threadIdx.x & 31;
    if (w >= KK) return;
    float2 v = *(const float2*)(emb + (size_t)w * DD + lane * 2);
    float ss = warpsum(v.x * v.x + v.y * v.y);
    float inv = 1.0f / fmaxf(sqrtf(ss), EPSV);
    float e0 = v.x * inv, e1 = v.y * inv;
    *(float2*)(g_en + (size_t)w * DD + lane * 2) = make_float2(e0, e1);
    g_ehf[w * 32 + lane] = pack2h(__float2half_rn(e0), __float2half_rn(e1));
}

// ---------------- kernel 2: K=128 fp16 z-split mma GEMM + certified top-4 ----------------
// A phase: 128 rows x 68 u32 stride (272B -> 4-bank shift/row -> conflict-free ldmatrix)
// B phase: 256 rows x 36 u32 stride (144B)
#define AROW 68
#define BROW 36
#define SMEM_BYTES (256 * BROW * 4)   // 36864 >= 128*68*4 = 34816

__global__ __launch_bounds__(256, 2) void k_sim(const float* __restrict__ ze) {
    extern __shared__ __align__(16) unsigned sB[];
    const int tid = threadIdx.x, wid = tid >> 5, lane = tid & 31;
    const int row0 = blockIdx.x * 128;
    const uint32_t sbase = smem_u32(sB);

    // ---- phase A: normalize z rows, fp16 hi/lo split, store [row][hi(32) | lo(32)] ----
#pragma unroll 1
    for (int it = 0; it < 16; it++) {
        int r = wid + it * 8;
        float2 v = *(const float2*)(ze + (size_t)(row0 + r) * 64 + lane * 2);
        float ss = warpsum(v.x * v.x + v.y * v.y);
        float den = fmaxf(sqrtf(ss), EPSV);
        float inv = 1.0f / den;
        if (lane == 0) g_znorm[row0 + r] = den;
        float z0 = v.x * inv, z1 = v.y * inv;
        __half h0 = __float2half_rn(z0), h1 = __float2half_rn(z1);
        float l0 = z0 - __half2float(h0), l1 = z1 - __half2float(h1);
        sB[r * AROW + lane]      = pack2h(h0, h1);
        sB[r * AROW + 32 + lane] = pack2h(__float2half_rn(l0), __float2half_rn(l1));
    }
    __syncthreads();

    // ---- A fragments: warp owns rows m0..m0+15; ksteps 0..3 = z_hi, 4..7 = z_lo ----
    const int m0 = wid * 16;
    uint32_t af[8][4];
    {
        uint32_t aaddr = sbase + (uint32_t)(m0 + (lane & 15)) * (AROW * 4) + ((lane >> 4) << 4);
#pragma unroll
        for (int ks = 0; ks < 8; ks++)
            LDSM4(af[ks][0], af[ks][1], af[ks][2], af[ks][3], aaddr + ks * 32);
    }
    __syncthreads();   // done reading A region -> reuse buffer for B

    // top-4 state for rows (m0 + lane/4) [a] and (m0 + lane/4 + 8) [b]
    float Va[4] = {-1e30f, -1e30f, -1e30f, -1e30f};
    int   Ia[4] = {0, 0, 0, 0};
    float Vb[4] = {-1e30f, -1e30f, -1e30f, -1e30f};
    int   Ib[4] = {0, 0, 0, 0};

#pragma unroll 1
    for (int c = 0; c < 4; c++) {
        // fill B chunk: 256 codes x 32 u32 of e_hi (coalesced)
#pragma unroll
        for (int i = 0; i < 32; i++) {
            int idx = i * 256 + tid;
            int n = idx >> 5, p = idx & 31;
            sB[n * BROW + p] = g_ehf[(size_t)(c * 256 + n) * 32 + p];
        }
        __syncthreads();

#pragma unroll 1
        for (int np = 0; np < 16; np++) {
            const int n0 = np * 16;
            float c0a[4] = {0,0,0,0}, c0b[4] = {0,0,0,0};
            float c1a[4] = {0,0,0,0}, c1b[4] = {0,0,0,0};
            uint32_t baddr = sbase +
                (uint32_t)(n0 + ((lane >> 4) << 3) + (lane & 7)) * (BROW * 4) +
                ((lane & 8) << 1);
            uint32_t bb[2][4];
            LDSM4(bb[0][0], bb[0][1], bb[0][2], bb[0][3], baddr);
#pragma unroll
            for (int ks = 0; ks < 4; ks++) {
                if (ks < 3)
                    LDSM4(bb[(ks + 1) & 1][0], bb[(ks + 1) & 1][1],
                          bb[(ks + 1) & 1][2], bb[(ks + 1) & 1][3], baddr + (ks + 1) * 32);
                uint32_t* b = bb[ks & 1];
                MMA16816(c0a, af[ks],     b[0], b[1]);   // z_hi . e_hi
                MMA16816(c1a, af[ks],     b[2], b[3]);
                MMA16816(c0b, af[ks + 4], b[0], b[1]);   // z_lo . e_hi
                MMA16816(c1b, af[ks + 4], b[2], b[3]);
            }
            float c0[4], c1[4];
#pragma unroll
            for (int j = 0; j < 4; j++) { c0[j] = c0a[j] + c0b[j]; c1[j] = c1a[j] + c1b[j]; }

            int colb = c * 256 + n0 + 2 * (lane & 3);
            float mxa = fmaxf(fmaxf(c0[0], c0[1]), fmaxf(c1[0], c1[1]));
            if (mxa >= Va[3]) {
                ins4(c0[0], colb,     Va, Ia);
                ins4(c0[1], colb + 1, Va, Ia);
                ins4(c1[0], colb + 8, Va, Ia);
                ins4(c1[1], colb + 9, Va, Ia);
            }
            float mxb = fmaxf(fmaxf(c0[2], c0[3]), fmaxf(c1[2], c1[3]));
            if (mxb >= Vb[3]) {
                ins4(c0[2], colb,     Vb, Ib);
                ins4(c0[3], colb + 1, Vb, Ib);
                ins4(c1[2], colb + 8, Vb, Ib);
                ins4(c1[3], colb + 9, Vb, Ib);
            }
        }
        __syncthreads();
    }

    // ---- merge top-4 across the 4 threads of each quad (disjoint col sets) ----
#pragma unroll
    for (int o = 1; o <= 2; o <<= 1) {
#pragma unroll
        for (int j = 0; j < 4; j++) {
            float wv = __shfl_xor_sync(0xffffffffu, Va[j], o);
            int   wi = __shfl_xor_sync(0xffffffffu, Ia[j], o);
            ins4(wv, wi, Va, Ia);
            float xv = __shfl_xor_sync(0xffffffffu, Vb[j], o);
            int   xi = __shfl_xor_sync(0xffffffffu, Ib[j], o);
            ins4(xv, xi, Vb, Ib);
        }
    }
    if ((lane & 3) == 0) {
        int ra = row0 + m0 + (lane >> 2);
        g_cand[ra]     = make_int4(Ia[0], Ia[1], Ia[2], Ia[3]);
        g_flag[ra]     = (Va[0] - Va[3] < MARGINF) ? 1 : 0;
        g_cand[ra + 8] = make_int4(Ib[0], Ib[1], Ib[2], Ib[3]);
        g_flag[ra + 8] = (Vb[0] - Vb[3] < MARGINF) ? 1 : 0;
    }
}

// ---------------- kernel 3: exact fp32 rescore (top-4 or certified fallback) + scatter ----------------
__global__ void k_rescore(const float* __restrict__ ze) {
    int w = (blockIdx.x * blockDim.x + threadIdx.x) >> 5;
    int lane = threadIdx.x & 31;
    if (w >= BB) return;
    float2 v = *(const float2*)(ze + (size_t)w * 64 + lane * 2);
    float ss = warpsum(v.x * v.x + v.y * v.y);
    float den = fmaxf(sqrtf(ss), EPSV);
    float inv = 1.0f / den;
    float zn0 = v.x * inv, zn1 = v.y * inv;

    float bv; int bi;
    if (g_flag[w]) {
        // margin not certified: full exact scan over all codes (rare)
        bv = -1e30f; bi = 0;
#pragma unroll 1
        for (int c = 0; c < KK; c++) {
            float2 e = *(const float2*)(g_en + (size_t)c * 64 + lane * 2);
            float d = warpsum(zn0 * e.x + zn1 * e.y);
            if (d > bv) { bv = d; bi = c; }   // ascending scan -> first occurrence on tie
        }
    } else {
        int4 cd = g_cand[w];
        float2 e0 = *(const float2*)(g_en + (size_t)cd.x * 64 + lane * 2);
        float2 e1 = *(const float2*)(g_en + (size_t)cd.y * 64 + lane * 2);
        float2 e2 = *(const float2*)(g_en + (size_t)cd.z * 64 + lane * 2);
        float2 e3 = *(const float2*)(g_en + (size_t)cd.w * 64 + lane * 2);
        float d0 = warpsum(zn0 * e0.x + zn1 * e0.y);
        float d1 = warpsum(zn0 * e1.x + zn1 * e1.y);
        float d2 = warpsum(zn0 * e2.x + zn1 * e2.y);
        float d3 = warpsum(zn0 * e3.x + zn1 * e3.y);
        bv = d0; bi = cd.x;
        if (d1 > bv || (d1 == bv && cd.y < bi)) { bv = d1; bi = cd.y; }
        if (d2 > bv || (d2 == bv && cd.z < bi)) { bv = d2; bi = cd.z; }
        if (d3 > bv || (d3 == bv && cd.w < bi)) { bv = d3; bi = cd.w; }
    }
    if (lane == 0) {
        g_codes[w] = bi;
        atomicAdd(&g_counts[bi], 1.0f);
    }
    atomicAdd(&g_dw[bi * 64 + 2 * lane],     zn0);
    atomicAdd(&g_dw[bi * 64 + 2 * lane + 1], zn1);
}

// ---------------- kernel 4: EMA + codebook re-normalize (16 CTAs) ----------------
__global__ void k_ema(const float* __restrict__ ema_cs, const float* __restrict__ ema_w) {
    __shared__ float sred[256];
    int tid = threadIdx.x;
    float part = 0.0f;
#pragma unroll
    for (int i = 0; i < 4; i++) {
        int k = tid + i * 256;
        part += ema_cs[k] * DECAYF + g_counts[k] * OMDF;
    }
    sred[tid] = part;
    __syncthreads();
    for (int s = 128; s > 0; s >>= 1) {
        if (tid < s) sred[tid] += sred[tid + s];
        __syncthreads();
    }
    float n = sred[0];

    int lane = tid & 15;
#pragma unroll 1
    for (int g = 0; g < 4; g++) {
        int k2 = blockIdx.x * 64 + g * 16 + (tid >> 4);
        float cs = ema_cs[k2] * DECAYF + g_counts[k2] * OMDF;
        float cluster = (cs + EPSV) / (n + KK * EPSV) * n;
        float inv = 1.0f / fmaxf(cluster, EPSV);
        float4 w = *(const float4*)(ema_w + (size_t)k2 * 64 + lane * 4);
        float4 dv = *(const float4*)(g_dw + (size_t)k2 * 64 + lane * 4);
        float4 m;
        m.x = (w.x * DECAYF + dv.x * OMDF) * inv;
        m.y = (w.y * DECAYF + dv.y * OMDF) * inv;
        m.z = (w.z * DECAYF + dv.z * OMDF) * inv;
        m.w = (w.w * DECAYF + dv.w * OMDF) * inv;
        float ss = group16sum(m.x * m.x + m.y * m.y + m.z * m.z + m.w * m.w);
        float ni = 1.0f / fmaxf(sqrtf(ss), EPSV);
        *(float4*)(g_embed_unit + (size_t)k2 * 64 + lane * 4) =
            make_float4(m.x * ni, m.y * ni, m.z * ni, m.w * ni);
    }
}

// ---------------- kernel 5: gather + outputs ----------------
__global__ void k_out(const float* __restrict__ ze, float* __restrict__ out, int write_aux) {
    int w = (blockIdx.x * blockDim.x + threadIdx.x) >> 5;
    int lane = threadIdx.x & 31;
    if (w >= BB) return;
    int c = g_codes[w];
    float zl = g_znorm[w];
    float zinv = 1.0f / zl;
    float2 e = *(const float2*)(g_embed_unit + (size_t)c * 64 + lane * 2);
    float ss = warpsum(e.x * e.x + e.y * e.y);
    float ed = fmaxf(sqrtf(ss), EPSV);
    float2 en = make_float2(e.x / ed, e.y / ed);
    float2 zev = *(const float2*)(ze + (size_t)w * 64 + lane * 2);
    float2 zn = make_float2(zev.x * zinv, zev.y * zinv);
    float dot = warpsum(zn.x * en.x + zn.y * en.y);
    float2 zq = make_float2(e.x * zl, e.y * zl);
    float2 o = make_float2(zev.x + (zq.x - zev.x), zev.y + (zq.y - zev.y));
    *(float2*)(out + (size_t)w * 64 + lane * 2) = o;
    if (write_aux && lane == 0) {
        out[(size_t)BB * DD + w] = (float)c;
        out[(size_t)BB * DD + BB + w] = 1.0f - dot;
    }
}

// ---------------- launcher ----------------
extern "C" void kernel_launch(void* const* d_in, const int* in_sizes, int n_in,
                              void* d_out, int out_size) {
    const float* ze  = (const float*)d_in[0];
    const float* emb = (const float*)d_in[1];
    const float* ecs = (const float*)d_in[2];
    const float* ew  = (const float*)d_in[3];
    float* out = (float*)d_out;

    long long need = (long long)BB * DD + 2LL * BB;
    int write_aux = ((long long)out_size >= need) ? 1 : 0;

    cudaFuncSetAttribute(k_sim, cudaFuncAttributeMaxDynamicSharedMemorySize, SMEM_BYTES);

    k_prep<<<ZERO_BLOCKS + KK / 8, 256>>>(emb);
    k_sim<<<BB / 128, 256, SMEM_BYTES>>>(ze);
    k_rescore<<<BB / 8, 256>>>(ze);
    k_ema<<<16, 256>>>(ecs, ew);
    k_out<<<BB / 8, 256>>>(ze, out, write_aux);
}

// round 16
// speedup vs baseline: 1.8812x; 1.8812x over previous
#include <cuda_runtime.h>
#include <cuda_fp16.h>
#include <math.h>
#include <stdint.h>

// Problem constants
#define BB 131072
#define DD 64
#define KK 1024
#define DECAYF 0.99f
#define OMDF 0.01f
#define EPSV 1e-5f
// |approx - exact| <= 2^-12 + slack; certify top-1 when v1 - v2 > MARGINF
#define MARGINF 6.0e-4f

// ---------------- scratch ----------------
__device__ float    g_en[KK * DD];        // normalized embedding fp32 (exact fallback)
__device__ unsigned g_ehf[KK * 32];       // e_hi rows as fp16x2 (64 fp16 -> 32 u32 per code)
__device__ float    g_counts[KK];
__device__ float    g_dw[KK * DD];
__device__ float    g_embed_unit[KK * DD];
__device__ float    g_znorm[BB];
__device__ int      g_codes[BB];
__device__ int      g_t1[BB];             // certified argmax candidate
__device__ int      g_flag[BB];           // 1 = margin not certified -> exact scan

// ---------------- helpers ----------------
__device__ __forceinline__ float warpsum(float v) {
#pragma unroll
    for (int o = 16; o; o >>= 1) v += __shfl_xor_sync(0xffffffffu, v, o);
    return v;
}
__device__ __forceinline__ float group16sum(float v) {
#pragma unroll
    for (int o = 8; o; o >>= 1) v += __shfl_xor_sync(0xffffffffu, v, o);
    return v;
}
__device__ __forceinline__ uint32_t smem_u32(const void* p) {
    uint32_t a;
    asm("{ .reg .u64 t; cvta.to.shared.u64 t, %1; cvt.u32.u64 %0, t; }" : "=r"(a) : "l"(p));
    return a;
}
__device__ __forceinline__ unsigned pack2h(__half a, __half b) {
    __half2 h = __halves2half2(a, b);
    return *reinterpret_cast<unsigned*>(&h);
}
// top-2 update; idx ascending within thread -> strict > keeps first occurrence.
// tie with top (v == v1) falls into second branch -> v2 = v1 -> margin 0 -> flagged.
__device__ __forceinline__ void upd2(float v, int i, float& v1, int& i1, float& v2) {
    if (v > v1) { v2 = v1; v1 = v; i1 = i; }
    else if (v > v2) { v2 = v; }
}
#define LDSM4(r0, r1, r2, r3, addr) \
    asm volatile("ldmatrix.sync.aligned.m8n8.x4.shared.b16 {%0,%1,%2,%3}, [%4];" \
        : "=r"(r0), "=r"(r1), "=r"(r2), "=r"(r3) : "r"(addr))
#define MMA16816(c, a, b0, b1) \
    asm volatile("mma.sync.aligned.m16n8k16.row.col.f32.f16.f16.f32 " \
        "{%0,%1,%2,%3}, {%4,%5,%6,%7}, {%8,%9}, {%0,%1,%2,%3};" \
        : "+f"((c)[0]), "+f"((c)[1]), "+f"((c)[2]), "+f"((c)[3]) \
        : "r"((a)[0]), "r"((a)[1]), "r"((a)[2]), "r"((a)[3]), "r"(b0), "r"(b1))

// ---------------- kernel 1: prep = zero scratch + normalize embedding ----------------
#define ZERO_BLOCKS 260
__global__ void k_prep(const float* __restrict__ emb) {
    int bid = blockIdx.x;
    if (bid < ZERO_BLOCKS) {
        int idx = bid * 256 + threadIdx.x;
        if (idx < KK * DD) g_dw[idx] = 0.0f;
        else if (idx < KK * DD + KK) g_counts[idx - KK * DD] = 0.0f;
        return;
    }
    int w = (bid - ZERO_BLOCKS) * 8 + (threadIdx.x >> 5);
    int lane = threadIdx.x & 31;
    if (w >= KK) return;
    float2 v = *(const float2*)(emb + (size_t)w * DD + lane * 2);
    float ss = warpsum(v.x * v.x + v.y * v.y);
    float inv = 1.0f / fmaxf(sqrtf(ss), EPSV);
    float e0 = v.x * inv, e1 = v.y * inv;
    *(float2*)(g_en + (size_t)w * DD + lane * 2) = make_float2(e0, e1);
    g_ehf[w * 32 + lane] = pack2h(__float2half_rn(e0), __float2half_rn(e1));
}

// ---------------- kernel 2: K=128 fp16 z-split mma GEMM + certified top-1 ----------------
// A phase: 128 rows x 68 u32 stride (272B -> 4-bank shift/row -> conflict-free ldmatrix)
// B phase: 256 rows x 36 u32 stride (144B)
#define AROW 68
#define BROW 36
#define SMEM_BYTES (256 * BROW * 4)   // 36864 >= 128*68*4 = 34816

__global__ __launch_bounds__(256, 2) void k_sim(const float* __restrict__ ze) {
    extern __shared__ __align__(16) unsigned sB[];
    const int tid = threadIdx.x, wid = tid >> 5, lane = tid & 31;
    const int row0 = blockIdx.x * 128;
    const uint32_t sbase = smem_u32(sB);

    // ---- phase A: normalize z rows, fp16 hi/lo split, store [row][hi(32) | lo(32)] ----
#pragma unroll 1
    for (int it = 0; it < 16; it++) {
        int r = wid + it * 8;
        float2 v = *(const float2*)(ze + (size_t)(row0 + r) * 64 + lane * 2);
        float ss = warpsum(v.x * v.x + v.y * v.y);
        float den = fmaxf(sqrtf(ss), EPSV);
        float inv = 1.0f / den;
        if (lane == 0) g_znorm[row0 + r] = den;
        float z0 = v.x * inv, z1 = v.y * inv;
        __half h0 = __float2half_rn(z0), h1 = __float2half_rn(z1);
        float l0 = z0 - __half2float(h0), l1 = z1 - __half2float(h1);
        sB[r * AROW + lane]      = pack2h(h0, h1);
        sB[r * AROW + 32 + lane] = pack2h(__float2half_rn(l0), __float2half_rn(l1));
    }
    __syncthreads();

    // ---- A fragments: warp owns rows m0..m0+15; ksteps 0..3 = z_hi, 4..7 = z_lo ----
    const int m0 = wid * 16;
    uint32_t af[8][4];
    {
        uint32_t aaddr = sbase + (uint32_t)(m0 + (lane & 15)) * (AROW * 4) + ((lane >> 4) << 4);
#pragma unroll
        for (int ks = 0; ks < 8; ks++)
            LDSM4(af[ks][0], af[ks][1], af[ks][2], af[ks][3], aaddr + ks * 32);
    }
    __syncthreads();   // done reading A region -> reuse buffer for B

    // top-2 state for rows (m0 + lane/4) [a] and (m0 + lane/4 + 8) [b]
    float va1 = -1e30f, va2 = -1e30f; int ia1 = 0;
    float vb1 = -1e30f, vb2 = -1e30f; int ib1 = 0;

#pragma unroll 1
    for (int c = 0; c < 4; c++) {
        // fill B chunk: 256 codes x 32 u32 of e_hi (coalesced)
#pragma unroll
        for (int i = 0; i < 32; i++) {
            int idx = i * 256 + tid;
            int n = idx >> 5, p = idx & 31;
            sB[n * BROW + p] = g_ehf[(size_t)(c * 256 + n) * 32 + p];
        }
        __syncthreads();

#pragma unroll 1
        for (int np = 0; np < 16; np++) {
            const int n0 = np * 16;
            float c0a[4] = {0,0,0,0}, c0b[4] = {0,0,0,0};
            float c1a[4] = {0,0,0,0}, c1b[4] = {0,0,0,0};
            uint32_t baddr = sbase +
                (uint32_t)(n0 + ((lane >> 4) << 3) + (lane & 7)) * (BROW * 4) +
                ((lane & 8) << 1);
            uint32_t bb[2][4];
            LDSM4(bb[0][0], bb[0][1], bb[0][2], bb[0][3], baddr);
#pragma unroll
            for (int ks = 0; ks < 4; ks++) {
                if (ks < 3)
                    LDSM4(bb[(ks + 1) & 1][0], bb[(ks + 1) & 1][1],
                          bb[(ks + 1) & 1][2], bb[(ks + 1) & 1][3], baddr + (ks + 1) * 32);
                uint32_t* b = bb[ks & 1];
                MMA16816(c0a, af[ks],     b[0], b[1]);   // z_hi . e_hi
                MMA16816(c1a, af[ks],     b[2], b[3]);
                MMA16816(c0b, af[ks + 4], b[0], b[1]);   // z_lo . e_hi
                MMA16816(c1b, af[ks + 4], b[2], b[3]);
            }
            float c0[4], c1[4];
#pragma unroll
            for (int j = 0; j < 4; j++) { c0[j] = c0a[j] + c0b[j]; c1[j] = c1a[j] + c1b[j]; }

            int colb = c * 256 + n0 + 2 * (lane & 3);
            float mxa = fmaxf(fmaxf(c0[0], c0[1]), fmaxf(c1[0], c1[1]));
            if (mxa > va2) {
                upd2(c0[0], colb,     va1, ia1, va2);
                upd2(c0[1], colb + 1, va1, ia1, va2);
                upd2(c1[0], colb + 8, va1, ia1, va2);
                upd2(c1[1], colb + 9, va1, ia1, va2);
            }
            float mxb = fmaxf(fmaxf(c0[2], c0[3]), fmaxf(c1[2], c1[3]));
            if (mxb > vb2) {
                upd2(c0[2], colb,     vb1, ib1, vb2);
                upd2(c0[3], colb + 1, vb1, ib1, vb2);
                upd2(c1[2], colb + 8, vb1, ib1, vb2);
                upd2(c1[3], colb + 9, vb1, ib1, vb2);
            }
        }
        __syncthreads();
    }

    // ---- merge top-2 across the 4 threads of each quad (disjoint col sets) ----
#pragma unroll
    for (int o = 1; o <= 2; o <<= 1) {
        float w1 = __shfl_xor_sync(0xffffffffu, va1, o);
        int   j1 = __shfl_xor_sync(0xffffffffu, ia1, o);
        float w2 = __shfl_xor_sync(0xffffffffu, va2, o);
        if (w1 > va1)       { va2 = fmaxf(va1, w2); va1 = w1; ia1 = j1; }
        else if (w1 == va1) { va2 = va1; ia1 = min(ia1, j1); }   // distinct-code tie -> flag
        else                { va2 = fmaxf(va2, w1); }
        float x1 = __shfl_xor_sync(0xffffffffu, vb1, o);
        int   k1 = __shfl_xor_sync(0xffffffffu, ib1, o);
        float x2 = __shfl_xor_sync(0xffffffffu, vb2, o);
        if (x1 > vb1)       { vb2 = fmaxf(vb1, x2); vb1 = x1; ib1 = k1; }
        else if (x1 == vb1) { vb2 = vb1; ib1 = min(ib1, k1); }
        else                { vb2 = fmaxf(vb2, x1); }
    }
    if ((lane & 3) == 0) {
        int ra = row0 + m0 + (lane >> 2);
        g_t1[ra]       = ia1;
        g_flag[ra]     = (va1 - va2 < MARGINF) ? 1 : 0;
        g_t1[ra + 8]   = ib1;
        g_flag[ra + 8] = (vb1 - vb2 < MARGINF) ? 1 : 0;
    }
}

// ---------------- kernel 3: certified code (or exact fallback scan) + scatter ----------------
__global__ void k_rescore(const float* __restrict__ ze) {
    __shared__ float zs[8][64];   // per-warp z_n staging for fallback scans
    int wm = threadIdx.x >> 5;
    int w = (blockIdx.x * blockDim.x + threadIdx.x) >> 5;
    int lane = threadIdx.x & 31;
    if (w >= BB) return;
    float2 v = *(const float2*)(ze + (size_t)w * 64 + lane * 2);
    float ss = warpsum(v.x * v.x + v.y * v.y);
    float den = fmaxf(sqrtf(ss), EPSV);
    float inv = 1.0f / den;
    float zn0 = v.x * inv, zn1 = v.y * inv;

    int bi;
    if (g_flag[w]) {
        // exact full scan, lane-parallel: lane L handles codes s*32 + L
        zs[wm][2 * lane] = zn0; zs[wm][2 * lane + 1] = zn1;
        __syncwarp();
        float bv = -1e30f; int bl = 0;
#pragma unroll 1
        for (int s = 0; s < 32; s++) {
            int cidx = s * 32 + lane;
            const float4* er = (const float4*)(g_en + (size_t)cidx * 64);
            float acc = 0.0f;
#pragma unroll
            for (int q = 0; q < 16; q++) {
                float4 e = er[q];
                acc += zs[wm][4 * q] * e.x + zs[wm][4 * q + 1] * e.y +
                       zs[wm][4 * q + 2] * e.z + zs[wm][4 * q + 3] * e.w;
            }
            if (acc > bv || (acc == bv && cidx < bl)) { bv = acc; bl = cidx; }
        }
        // cross-lane argmax, tie -> lower index
#pragma unroll
        for (int o = 16; o; o >>= 1) {
            float qv = __shfl_xor_sync(0xffffffffu, bv, o);
            int   qi = __shfl_xor_sync(0xffffffffu, bl, o);
            if (qv > bv || (qv == bv && qi < bl)) { bv = qv; bl = qi; }
        }
        bi = bl;
    } else {
        bi = g_t1[w];   // certified exact argmax
    }
    if (lane == 0) {
        g_codes[w] = bi;
        atomicAdd(&g_counts[bi], 1.0f);
    }
    atomicAdd(&g_dw[bi * 64 + 2 * lane],     zn0);
    atomicAdd(&g_dw[bi * 64 + 2 * lane + 1], zn1);
}

// ---------------- kernel 4: EMA + codebook re-normalize (16 CTAs) ----------------
__global__ void k_ema(const float* __restrict__ ema_cs, const float* __restrict__ ema_w) {
    __shared__ float sred[256];
    int tid = threadIdx.x;
    float part = 0.0f;
#pragma unroll
    for (int i = 0; i < 4; i++) {
        int k = tid + i * 256;
        part += ema_cs[k] * DECAYF + g_counts[k] * OMDF;
    }
    sred[tid] = part;
    __syncthreads();
    for (int s = 128; s > 0; s >>= 1) {
        if (tid < s) sred[tid] += sred[tid + s];
        __syncthreads();
    }
    float n = sred[0];

    int lane = tid & 15;
#pragma unroll 1
    for (int g = 0; g < 4; g++) {
        int k2 = blockIdx.x * 64 + g * 16 + (tid >> 4);
        float cs = ema_cs[k2] * DECAYF + g_counts[k2] * OMDF;
        float cluster = (cs + EPSV) / (n + KK * EPSV) * n;
        float inv = 1.0f / fmaxf(cluster, EPSV);
        float4 w = *(const float4*)(ema_w + (size_t)k2 * 64 + lane * 4);
        float4 dv = *(const float4*)(g_dw + (size_t)k2 * 64 + lane * 4);
        float4 m;
        m.x = (w.x * DECAYF + dv.x * OMDF) * inv;
        m.y = (w.y * DECAYF + dv.y * OMDF) * inv;
        m.z = (w.z * DECAYF + dv.z * OMDF) * inv;
        m.w = (w.w * DECAYF + dv.w * OMDF) * inv;
        float ss = group16sum(m.x * m.x + m.y * m.y + m.z * m.z + m.w * m.w);
        float ni = 1.0f / fmaxf(sqrtf(ss), EPSV);
        *(float4*)(g_embed_unit + (size_t)k2 * 64 + lane * 4) =
            make_float4(m.x * ni, m.y * ni, m.z * ni, m.w * ni);
    }
}

// ---------------- kernel 5: gather + outputs ----------------
__global__ void k_out(const float* __restrict__ ze, float* __restrict__ out, int write_aux) {
    int w = (blockIdx.x * blockDim.x + threadIdx.x) >> 5;
    int lane = threadIdx.x & 31;
    if (w >= BB) return;
    int c = g_codes[w];
    float zl = g_znorm[w];
    float zinv = 1.0f / zl;
    float2 e = *(const float2*)(g_embed_unit + (size_t)c * 64 + lane * 2);
    float ss = warpsum(e.x * e.x + e.y * e.y);
    float ed = fmaxf(sqrtf(ss), EPSV);
    float2 en = make_float2(e.x / ed, e.y / ed);
    float2 zev = *(const float2*)(ze + (size_t)w * 64 + lane * 2);
    float2 zn = make_float2(zev.x * zinv, zev.y * zinv);
    float dot = warpsum(zn.x * en.x + zn.y * en.y);
    float2 zq = make_float2(e.x * zl, e.y * zl);
    float2 o = make_float2(zev.x + (zq.x - zev.x), zev.y + (zq.y - zev.y));
    *(float2*)(out + (size_t)w * 64 + lane * 2) = o;
    if (write_aux && lane == 0) {
        out[(size_t)BB * DD + w] = (float)c;
        out[(size_t)BB * DD + BB + w] = 1.0f - dot;
    }
}

// ---------------- launcher ----------------
extern "C" void kernel_launch(void* const* d_in, const int* in_sizes, int n_in,
                              void* d_out, int out_size) {
    const float* ze  = (const float*)d_in[0];
    const float* emb = (const float*)d_in[1];
    const float* ecs = (const float*)d_in[2];
    const float* ew  = (const float*)d_in[3];
    float* out = (float*)d_out;

    long long need = (long long)BB * DD + 2LL * BB;
    int write_aux = ((long long)out_size >= need) ? 1 : 0;

    cudaFuncSetAttribute(k_sim, cudaFuncAttributeMaxDynamicSharedMemorySize, SMEM_BYTES);

    k_prep<<<ZERO_BLOCKS + KK / 8, 256>>>(emb);
    k_sim<<<BB / 128, 256, SMEM_BYTES>>>(ze);
    k_rescore<<<BB / 8, 256>>>(ze);
    k_ema<<<16, 256>>>(ecs, ew);
    k_out<<<BB / 8, 256>>>(ze, out, write_aux);
}

// round 17
// speedup vs baseline: 2.0062x; 1.0665x over previous
#include <cuda_runtime.h>
#include <cuda_fp16.h>
#include <math.h>
#include <stdint.h>

// Problem constants
#define BB 131072
#define DD 64
#define KK 1024
#define DECAYF 0.99f
#define OMDF 0.01f
#define EPSV 1e-5f
// |approx - exact| <= ~2.5e-4; certify top-1 when v1 - v2 > MARGINF
#define MARGINF 6.0e-4f

// ---------------- scratch ----------------
__device__ float    g_en[KK * DD];        // normalized embedding fp32 (exact fallback)
__device__ unsigned g_ehf[KK * 32];       // e_hi rows as fp16x2 (64 fp16 -> 32 u32 per code)
__device__ float    g_counts[KK];
__device__ float    g_dw[KK * DD];
__device__ float    g_embed_unit[KK * DD];
__device__ float    g_znorm[BB];
__device__ int      g_codes[BB];
__device__ int      g_t1[BB];             // certified argmax candidate
__device__ int      g_flag[BB];           // 1 = margin not certified -> exact scan

// ---------------- helpers ----------------
__device__ __forceinline__ float warpsum(float v) {
#pragma unroll
    for (int o = 16; o; o >>= 1) v += __shfl_xor_sync(0xffffffffu, v, o);
    return v;
}
__device__ __forceinline__ float group16sum(float v) {
#pragma unroll
    for (int o = 8; o; o >>= 1) v += __shfl_xor_sync(0xffffffffu, v, o);
    return v;
}
__device__ __forceinline__ uint32_t smem_u32(const void* p) {
    uint32_t a;
    asm("{ .reg .u64 t; cvta.to.shared.u64 t, %1; cvt.u32.u64 %0, t; }" : "=r"(a) : "l"(p));
    return a;
}
__device__ __forceinline__ unsigned pack2h(__half a, __half b) {
    __half2 h = __halves2half2(a, b);
    return *reinterpret_cast<unsigned*>(&h);
}
// top-2 update; idx ascending within thread -> strict > keeps first occurrence.
// tie with top (v == v1) -> v2 = v1 -> margin 0 -> flagged -> exact fallback.
__device__ __forceinline__ void upd2(float v, int i, float& v1, int& i1, float& v2) {
    if (v > v1) { v2 = v1; v1 = v; i1 = i; }
    else if (v > v2) { v2 = v; }
}
#define LDSM4(r0, r1, r2, r3, addr) \
    asm volatile("ldmatrix.sync.aligned.m8n8.x4.shared.b16 {%0,%1,%2,%3}, [%4];" \
        : "=r"(r0), "=r"(r1), "=r"(r2), "=r"(r3) : "r"(addr))
#define MMA16816(c, a, b0, b1) \
    asm volatile("mma.sync.aligned.m16n8k16.row.col.f32.f16.f16.f32 " \
        "{%0,%1,%2,%3}, {%4,%5,%6,%7}, {%8,%9}, {%0,%1,%2,%3};" \
        : "+f"((c)[0]), "+f"((c)[1]), "+f"((c)[2]), "+f"((c)[3]) \
        : "r"((a)[0]), "r"((a)[1]), "r"((a)[2]), "r"((a)[3]), "r"(b0), "r"(b1))

// ---------------- dummy kernel (shifts ncu profile slot onto k_sim) ----------------
__global__ void k_nop() {}

// ---------------- kernel 1: prep = zero scratch + normalize embedding ----------------
#define ZERO_BLOCKS 260
__global__ void k_prep(const float* __restrict__ emb) {
    int bid = blockIdx.x;
    if (bid < ZERO_BLOCKS) {
        int idx = bid * 256 + threadIdx.x;
        if (idx < KK * DD) g_dw[idx] = 0.0f;
        else if (idx < KK * DD + KK) g_counts[idx - KK * DD] = 0.0f;
        return;
    }
    int w = (bid - ZERO_BLOCKS) * 8 + (threadIdx.x >> 5);
    int lane = threadIdx.x & 31;
    if (w >= KK) return;
    float2 v = *(const float2*)(emb + (size_t)w * DD + lane * 2);
    float ss = warpsum(v.x * v.x + v.y * v.y);
    float inv = 1.0f / fmaxf(sqrtf(ss), EPSV);
    float e0 = v.x * inv, e1 = v.y * inv;
    *(float2*)(g_en + (size_t)w * DD + lane * 2) = make_float2(e0, e1);
    g_ehf[w * 32 + lane] = pack2h(__float2half_rn(e0), __float2half_rn(e1));
}

// ---------------- kernel 2: K=128 fp16 z-split mma GEMM + certified top-1 ----------------
// A phase: 128 rows x 68 u32 stride (272B -> 4-bank shift/row -> conflict-free ldmatrix)
// B phase: 256 rows x 36 u32 stride (144B)
#define AROW 68
#define BROW 36
#define SMEM_BYTES (256 * BROW * 4)   // 36864 >= 128*68*4 = 34816

__global__ __launch_bounds__(256, 3) void k_sim(const float* __restrict__ ze) {
    extern __shared__ __align__(16) unsigned sB[];
    const int tid = threadIdx.x, wid = tid >> 5, lane = tid & 31;
    const int row0 = blockIdx.x * 128;
    const uint32_t sbase = smem_u32(sB);

    // ---- phase A: normalize z rows, fp16 hi/lo split, store [row][hi(32) | lo(32)] ----
#pragma unroll 1
    for (int it = 0; it < 16; it++) {
        int r = wid + it * 8;
        float2 v = *(const float2*)(ze + (size_t)(row0 + r) * 64 + lane * 2);
        float ss = warpsum(v.x * v.x + v.y * v.y);
        float den = fmaxf(sqrtf(ss), EPSV);
        float inv = 1.0f / den;
        if (lane == 0) g_znorm[row0 + r] = den;
        float z0 = v.x * inv, z1 = v.y * inv;
        __half h0 = __float2half_rn(z0), h1 = __float2half_rn(z1);
        float l0 = z0 - __half2float(h0), l1 = z1 - __half2float(h1);
        sB[r * AROW + lane]      = pack2h(h0, h1);
        sB[r * AROW + 32 + lane] = pack2h(__float2half_rn(l0), __float2half_rn(l1));
    }
    __syncthreads();

    // ---- A fragments: warp owns rows m0..m0+15; ksteps 0..3 = z_hi, 4..7 = z_lo ----
    const int m0 = wid * 16;
    uint32_t af[8][4];
    {
        uint32_t aaddr = sbase + (uint32_t)(m0 + (lane & 15)) * (AROW * 4) + ((lane >> 4) << 4);
#pragma unroll
        for (int ks = 0; ks < 8; ks++)
            LDSM4(af[ks][0], af[ks][1], af[ks][2], af[ks][3], aaddr + ks * 32);
    }
    __syncthreads();   // done reading A region -> reuse buffer for B

    // top-2 state for rows (m0 + lane/4) [a] and (m0 + lane/4 + 8) [b]
    float va1 = -1e30f, va2 = -1e30f; int ia1 = 0;
    float vb1 = -1e30f, vb2 = -1e30f; int ib1 = 0;

#pragma unroll 1
    for (int c = 0; c < 4; c++) {
        // fill B chunk: 256 codes x 32 u32 of e_hi (coalesced)
#pragma unroll
        for (int i = 0; i < 32; i++) {
            int idx = i * 256 + tid;
            int n = idx >> 5, p = idx & 31;
            sB[n * BROW + p] = g_ehf[(size_t)(c * 256 + n) * 32 + p];
        }
        __syncthreads();

#pragma unroll 1
        for (int np = 0; np < 16; np++) {
            const int n0 = np * 16;
            // 2 accumulator chains (n8-halves), depth 8 each
            float c0[4] = {0,0,0,0}, c1[4] = {0,0,0,0};
            uint32_t baddr = sbase +
                (uint32_t)(n0 + ((lane >> 4) << 3) + (lane & 7)) * (BROW * 4) +
                ((lane & 8) << 1);
            uint32_t bb[2][4];
            LDSM4(bb[0][0], bb[0][1], bb[0][2], bb[0][3], baddr);
#pragma unroll
            for (int ks = 0; ks < 4; ks++) {
                if (ks < 3)
                    LDSM4(bb[(ks + 1) & 1][0], bb[(ks + 1) & 1][1],
                          bb[(ks + 1) & 1][2], bb[(ks + 1) & 1][3], baddr + (ks + 1) * 32);
                uint32_t* b = bb[ks & 1];
                MMA16816(c0, af[ks],     b[0], b[1]);   // z_hi . e_hi
                MMA16816(c0, af[ks + 4], b[0], b[1]);   // z_lo . e_hi
                MMA16816(c1, af[ks],     b[2], b[3]);
                MMA16816(c1, af[ks + 4], b[2], b[3]);
            }

            int colb = c * 256 + n0 + 2 * (lane & 3);
            float mxa = fmaxf(fmaxf(c0[0], c0[1]), fmaxf(c1[0], c1[1]));
            if (mxa > va2) {
                upd2(c0[0], colb,     va1, ia1, va2);
                upd2(c0[1], colb + 1, va1, ia1, va2);
                upd2(c1[0], colb + 8, va1, ia1, va2);
                upd2(c1[1], colb + 9, va1, ia1, va2);
            }
            float mxb = fmaxf(fmaxf(c0[2], c0[3]), fmaxf(c1[2], c1[3]));
            if (mxb > vb2) {
                upd2(c0[2], colb,     vb1, ib1, vb2);
                upd2(c0[3], colb + 1, vb1, ib1, vb2);
                upd2(c1[2], colb + 8, vb1, ib1, vb2);
                upd2(c1[3], colb + 9, vb1, ib1, vb2);
            }
        }
        __syncthreads();
    }

    // ---- merge top-2 across the 4 threads of each quad (disjoint col sets) ----
#pragma unroll
    for (int o = 1; o <= 2; o <<= 1) {
        float w1 = __shfl_xor_sync(0xffffffffu, va1, o);
        int   j1 = __shfl_xor_sync(0xffffffffu, ia1, o);
        float w2 = __shfl_xor_sync(0xffffffffu, va2, o);
        if (w1 > va1)       { va2 = fmaxf(va1, w2); va1 = w1; ia1 = j1; }
        else if (w1 == va1) { va2 = va1; ia1 = min(ia1, j1); }   // distinct-code tie -> flag
        else                { va2 = fmaxf(va2, w1); }
        float x1 = __shfl_xor_sync(0xffffffffu, vb1, o);
        int   k1 = __shfl_xor_sync(0xffffffffu, ib1, o);
        float x2 = __shfl_xor_sync(0xffffffffu, vb2, o);
        if (x1 > vb1)       { vb2 = fmaxf(vb1, x2); vb1 = x1; ib1 = k1; }
        else if (x1 == vb1) { vb2 = vb1; ib1 = min(ib1, k1); }
        else                { vb2 = fmaxf(vb2, x1); }
    }
    if ((lane & 3) == 0) {
        int ra = row0 + m0 + (lane >> 2);
        g_t1[ra]       = ia1;
        g_flag[ra]     = (va1 - va2 < MARGINF) ? 1 : 0;
        g_t1[ra + 8]   = ib1;
        g_flag[ra + 8] = (vb1 - vb2 < MARGINF) ? 1 : 0;
    }
}

// ---------------- kernel 3: certified code (or exact fallback scan) + scatter ----------------
__global__ void k_rescore(const float* __restrict__ ze) {
    __shared__ float zs[8][64];   // per-warp z_n staging for fallback scans
    int wm = threadIdx.x >> 5;
    int w = (blockIdx.x * blockDim.x + threadIdx.x) >> 5;
    int lane = threadIdx.x & 31;
    if (w >= BB) return;
    float2 v = *(const float2*)(ze + (size_t)w * 64 + lane * 2);
    float ss = warpsum(v.x * v.x + v.y * v.y);
    float den = fmaxf(sqrtf(ss), EPSV);
    float inv = 1.0f / den;
    float zn0 = v.x * inv, zn1 = v.y * inv;

    int bi;
    if (g_flag[w]) {
        // exact full scan, lane-parallel: lane L handles codes s*32 + L
        zs[wm][2 * lane] = zn0; zs[wm][2 * lane + 1] = zn1;
        __syncwarp();
        float bv = -1e30f; int bl = 0;
#pragma unroll 1
        for (int s = 0; s < 32; s++) {
            int cidx = s * 32 + lane;
            const float4* er = (const float4*)(g_en + (size_t)cidx * 64);
            float acc = 0.0f;
#pragma unroll
            for (int q = 0; q < 16; q++) {
                float4 e = er[q];
                acc += zs[wm][4 * q] * e.x + zs[wm][4 * q + 1] * e.y +
                       zs[wm][4 * q + 2] * e.z + zs[wm][4 * q + 3] * e.w;
            }
            if (acc > bv || (acc == bv && cidx < bl)) { bv = acc; bl = cidx; }
        }
#pragma unroll
        for (int o = 16; o; o >>= 1) {
            float qv = __shfl_xor_sync(0xffffffffu, bv, o);
            int   qi = __shfl_xor_sync(0xffffffffu, bl, o);
            if (qv > bv || (qv == bv && qi < bl)) { bv = qv; bl = qi; }
        }
        bi = bl;
    } else {
        bi = g_t1[w];   // certified exact argmax
    }
    if (lane == 0) {
        g_codes[w] = bi;
        atomicAdd(&g_counts[bi], 1.0f);
    }
    atomicAdd(&g_dw[bi * 64 + 2 * lane],     zn0);
    atomicAdd(&g_dw[bi * 64 + 2 * lane + 1], zn1);
}

// ---------------- kernel 4: EMA + codebook re-normalize (16 CTAs) ----------------
__global__ void k_ema(const float* __restrict__ ema_cs, const float* __restrict__ ema_w) {
    __shared__ float sred[256];
    int tid = threadIdx.x;
    float part = 0.0f;
#pragma unroll
    for (int i = 0; i < 4; i++) {
        int k = tid + i * 256;
        part += ema_cs[k] * DECAYF + g_counts[k] * OMDF;
    }
    sred[tid] = part;
    __syncthreads();
    for (int s = 128; s > 0; s >>= 1) {
        if (tid < s) sred[tid] += sred[tid + s];
        __syncthreads();
    }
    float n = sred[0];

    int lane = tid & 15;
#pragma unroll 1
    for (int g = 0; g < 4; g++) {
        int k2 = blockIdx.x * 64 + g * 16 + (tid >> 4);
        float cs = ema_cs[k2] * DECAYF + g_counts[k2] * OMDF;
        float cluster = (cs + EPSV) / (n + KK * EPSV) * n;
        float inv = 1.0f / fmaxf(cluster, EPSV);
        float4 w = *(const float4*)(ema_w + (size_t)k2 * 64 + lane * 4);
        float4 dv = *(const float4*)(g_dw + (size_t)k2 * 64 + lane * 4);
        float4 m;
        m.x = (w.x * DECAYF + dv.x * OMDF) * inv;
        m.y = (w.y * DECAYF + dv.y * OMDF) * inv;
        m.z = (w.z * DECAYF + dv.z * OMDF) * inv;
        m.w = (w.w * DECAYF + dv.w * OMDF) * inv;
        float ss = group16sum(m.x * m.x + m.y * m.y + m.z * m.z + m.w * m.w);
        float ni = 1.0f / fmaxf(sqrtf(ss), EPSV);
        *(float4*)(g_embed_unit + (size_t)k2 * 64 + lane * 4) =
            make_float4(m.x * ni, m.y * ni, m.z * ni, m.w * ni);
    }
}

// ---------------- kernel 5: gather + outputs ----------------
__global__ void k_out(const float* __restrict__ ze, float* __restrict__ out, int write_aux) {
    int w = (blockIdx.x * blockDim.x + threadIdx.x) >> 5;
    int lane = threadIdx.x & 31;
    if (w >= BB) return;
    int c = g_codes[w];
    float zl = g_znorm[w];
    float zinv = 1.0f / zl;
    float2 e = *(const float2*)(g_embed_unit + (size_t)c * 64 + lane * 2);
    float ss = warpsum(e.x * e.x + e.y * e.y);
    float ed = fmaxf(sqrtf(ss), EPSV);
    float2 en = make_float2(e.x / ed, e.y / ed);
    float2 zev = *(const float2*)(ze + (size_t)w * 64 + lane * 2);
    float2 zn = make_float2(zev.x * zinv, zev.y * zinv);
    float dot = warpsum(zn.x * en.x + zn.y * en.y);
    float2 zq = make_float2(e.x * zl, e.y * zl);
    float2 o = make_float2(zev.x + (zq.x - zev.x), zev.y + (zq.y - zev.y));
    *(float2*)(out + (size_t)w * 64 + lane * 2) = o;
    if (write_aux && lane == 0) {
        out[(size_t)BB * DD + w] = (float)c;
        out[(size_t)BB * DD + BB + w] = 1.0f - dot;
    }
}

// ---------------- launcher ----------------
extern "C" void kernel_launch(void* const* d_in, const int* in_sizes, int n_in,
                              void* d_out, int out_size) {
    const float* ze  = (const float*)d_in[0];
    const float* emb = (const float*)d_in[1];
    const float* ecs = (const float*)d_in[2];
    const float* ew  = (const float*)d_in[3];
    float* out = (float*)d_out;

    long long need = (long long)BB * DD + 2LL * BB;
    int write_aux = ((long long)out_size >= need) ? 1 : 0;

    cudaFuncSetAttribute(k_sim, cudaFuncAttributeMaxDynamicSharedMemorySize, SMEM_BYTES);

    k_prep<<<ZERO_BLOCKS + KK / 8, 256>>>(emb);
    k_nop<<<1, 32>>>();   // shift ncu's profile slot (launch #3) onto k_sim
    k_nop<<<1, 32>>>();
    k_sim<<<BB / 128, 256, SMEM_BYTES>>>(ze);
    k_rescore<<<BB / 8, 256>>>(ze);
    k_ema<<<16, 256>>>(ecs, ew);
    k_out<<<BB / 8, 256>>>(ze, out, write_aux);
}